// round 15
// baseline (speedup 1.0000x reference)
#include <cuda_runtime.h>
#include <cuda_fp16.h>
#include <cstdint>

#define D_IN 256
#define D_OUT 128
#define SEGSZ 64
#define N_SEQ 2048

namespace {
// Row strides in BYTES. All satisfy (stride/4) % 32 == 4 so that fragment
// loads across a warp (8 rows x 4 cols) hit banks 4*lr+lc -> conflict-free.
constexpr int X_STB = 528;    // X: 256 halves + pad
constexpr int H_STB = 272;    // h row-major: 128 halves + pad
constexpr int T_STB = 144;    // h transposed: 64 halves + pad
constexpr int P_STB = 144;    // P row-major: 64 halves + pad
constexpr int S_STF = 68;     // S fp32 stride in floats

// X region (33792 B) is dead after the GEMM mainloop; Ss and P overlay
// disjoint sub-ranges of it (17408 + 9216 = 26624 <= 33792).
constexpr int OFF_X  = 0;                   // 64*528  = 33792 B
constexpr int OFF_S  = 0;                   // 64*68*4 = 17408 B (overlay)
constexpr int OFF_P  = 17408;               // 64*144  =  9216 B (overlay)
constexpr int OFF_H  = 33792;               // 64*272  = 17408 B
constexpr int OFF_T  = OFF_H + 17408;       // 51200: 128*144 = 18432 B
constexpr int OFF_BS = OFF_T + 18432;       // 69632: 512 B
constexpr int SMEM_BYTES = OFF_BS + 512;    // 70144 B; x3 CTAs = 210432 B
} // namespace

// W in fp16 MMA B-fragment layout:
// g_wfrag16[(kk*16 + ng)*32 + lane] = uint2{
//   half2( W[kk*16+2lc  ][ng*8+lr], W[kk*16+2lc+1][ng*8+lr] ),
//   half2( W[kk*16+2lc+8][ng*8+lr], W[kk*16+2lc+9][ng*8+lr] ) }
__device__ uint2 g_wfrag16[16 * 16 * 32];   // 64 KB

__device__ __forceinline__ uint32_t h2bits(__half2 h) {
    return *reinterpret_cast<uint32_t*>(&h);
}

__device__ __forceinline__ void hmma(float* d, const uint32_t* a, const uint32_t* b) {
    asm volatile(
        "mma.sync.aligned.m16n8k16.row.col.f32.f16.f16.f32 "
        "{%0,%1,%2,%3}, {%4,%5,%6,%7}, {%8,%9}, {%0,%1,%2,%3};\n"
        : "+f"(d[0]), "+f"(d[1]), "+f"(d[2]), "+f"(d[3])
        : "r"(a[0]), "r"(a[1]), "r"(a[2]), "r"(a[3]), "r"(b[0]), "r"(b[1]));
}

__global__ __launch_bounds__(256)
void prep_w_kernel(const float* __restrict__ Wg) {
    int i = blockIdx.x * 256 + threadIdx.x;   // 0..8191
    int kk = i >> 9;          // 0..15
    int ng = (i >> 5) & 15;
    int ln = i & 31;
    int lr = ln >> 2, lc = ln & 3;
    int col = ng * 8 + lr;
    int k = kk * 16;
    __half2 b0 = __floats2half2_rn(Wg[(k + 2*lc    ) * D_OUT + col],
                                   Wg[(k + 2*lc + 1) * D_OUT + col]);
    __half2 b1 = __floats2half2_rn(Wg[(k + 2*lc + 8) * D_OUT + col],
                                   Wg[(k + 2*lc + 9) * D_OUT + col]);
    uint2 v;
    v.x = *reinterpret_cast<uint32_t*>(&b0);
    v.y = *reinterpret_cast<uint32_t*>(&b1);
    g_wfrag16[i] = v;
}

__global__ __launch_bounds__(256, 3)
void attn_hidden_kernel(const float* __restrict__ Xall,
                        const float* __restrict__ bg,
                        float* __restrict__ out)
{
    extern __shared__ char sm[];
    float* Ss = reinterpret_cast<float*>(sm + OFF_S);
    float* bs = reinterpret_cast<float*>(sm + OFF_BS);

    const int tid  = threadIdx.x;
    const int warp = tid >> 5;
    const int lane = tid & 31;
    const int lr   = lane >> 2;
    const int lc   = lane & 3;

    // 2x4 warp grid: GEMM/ctx warp tile = 32 rows x 32 cols; S: 32 x 16
    const int m0  = (warp & 1) * 32;
    const int nq  = warp >> 1;       // 0..3
    const int n0  = nq * 32;
    const int n0s = nq * 16;

    const int g = blockIdx.x;
    const float* Xg = Xall + (size_t)g * SEGSZ * D_IN;

    if (tid < D_OUT) bs[tid] = bg[tid];

    // ---- stage ALL of X (64x256) fp32 -> fp16 smem, once ----
    #pragma unroll 4
    for (int t = 0; t < 16; ++t) {
        int j = tid + t * 256;        // 0..4095 float4s (64 rows x 64 float4)
        int row = j >> 6, q = j & 63;
        float4 x4 = *reinterpret_cast<const float4*>(Xg + row * D_IN + q * 4);
        __half2 h0 = __floats2half2_rn(x4.x, x4.y);
        __half2 h1 = __floats2half2_rn(x4.z, x4.w);
        uint2 v; v.x = h2bits(h0); v.y = h2bits(h1);
        *reinterpret_cast<uint2*>(sm + OFF_X + row * X_STB + q * 8) = v;
    }

    // W B-fragment register ring: 2 slots, prefetch distance 2.
    // kk uses slot kk&1; the load for kk+2 is issued AFTER the MMAs that read
    // the slot (WAR), giving ~2 inner iterations to cover L1-miss -> L2 latency.
    uint32_t bfr[2][4][2];
    #pragma unroll
    for (int s = 0; s < 2; ++s) {
        #pragma unroll
        for (int nt = 0; nt < 4; ++nt) {
            uint2 w = __ldg(&g_wfrag16[(s * 16 + nq * 4 + nt) * 32 + lane]);
            bfr[s][nt][0] = w.x; bfr[s][nt][1] = w.y;
        }
    }

    __syncthreads();   // Xs + bs ready

    // ================= GEMM: h = X(64x256) @ W(256x128), 16 k16 steps ======
    float acc[2][4][4];
    #pragma unroll
    for (int mt = 0; mt < 2; ++mt)
        #pragma unroll
        for (int nt = 0; nt < 4; ++nt)
            #pragma unroll
            for (int i = 0; i < 4; ++i) acc[mt][nt][i] = 0.f;

    #pragma unroll
    for (int kk = 0; kk < 16; ++kk) {
        const int cur = kk & 1;
        uint32_t af[2][4];
        #pragma unroll
        for (int mt = 0; mt < 2; ++mt) {
            const char* p = sm + OFF_X + (m0 + mt * 16 + lr) * X_STB + kk * 32 + lc * 4;
            af[mt][0] = *reinterpret_cast<const uint32_t*>(p);
            af[mt][1] = *reinterpret_cast<const uint32_t*>(p + 8 * X_STB);
            af[mt][2] = *reinterpret_cast<const uint32_t*>(p + 16);
            af[mt][3] = *reinterpret_cast<const uint32_t*>(p + 8 * X_STB + 16);
        }
        #pragma unroll
        for (int mt = 0; mt < 2; ++mt)
            #pragma unroll
            for (int nt = 0; nt < 4; ++nt)
                hmma(acc[mt][nt], af[mt], bfr[cur][nt]);
        // prefetch W frags for kk+2 into the slot just consumed
        const int nk = (kk + 2 < 16) ? kk + 2 : 15;
        #pragma unroll
        for (int nt = 0; nt < 4; ++nt) {
            uint2 w = __ldg(&g_wfrag16[(nk * 16 + nq * 4 + nt) * 32 + lane]);
            bfr[cur][nt][0] = w.x; bfr[cur][nt][1] = w.y;
        }
    }

    // epilogue: h (+bias) -> fp16, stored row-major (hs) AND transposed (hT)
    #pragma unroll
    for (int mt = 0; mt < 2; ++mt) {
        #pragma unroll
        for (int nt = 0; nt < 4; ++nt) {
            int row = m0 + mt * 16 + lr;
            int col = n0 + nt * 8 + 2 * lc;
            float d0 = acc[mt][nt][0] + bs[col];
            float d1 = acc[mt][nt][1] + bs[col + 1];
            float d2 = acc[mt][nt][2] + bs[col];
            float d3 = acc[mt][nt][3] + bs[col + 1];
            __half2 p01 = __floats2half2_rn(d0, d1);
            __half2 p23 = __floats2half2_rn(d2, d3);
            *reinterpret_cast<uint32_t*>(sm + OFF_H + row * H_STB + col * 2)       = h2bits(p01);
            *reinterpret_cast<uint32_t*>(sm + OFF_H + (row + 8) * H_STB + col * 2) = h2bits(p23);
            __half* t0 = reinterpret_cast<__half*>(sm + OFF_T + col * T_STB);
            __half* t1 = reinterpret_cast<__half*>(sm + OFF_T + (col + 1) * T_STB);
            t0[row]     = __low2half(p01);  t1[row]     = __high2half(p01);
            t0[row + 8] = __low2half(p23);  t1[row + 8] = __high2half(p23);
        }
    }
    __syncthreads();

    // ================= S = h @ h^T  (64x64, K=128 -> 8 k16 steps) ==========
    float accS[2][2][4];
    #pragma unroll
    for (int mt = 0; mt < 2; ++mt)
        #pragma unroll
        for (int nt = 0; nt < 2; ++nt)
            #pragma unroll
            for (int i = 0; i < 4; ++i) accS[mt][nt][i] = 0.f;

    #pragma unroll
    for (int kk = 0; kk < 8; ++kk) {
        uint32_t af[2][4];
        #pragma unroll
        for (int mt = 0; mt < 2; ++mt) {
            const char* p = sm + OFF_H + (m0 + mt * 16 + lr) * H_STB + kk * 32 + lc * 4;
            af[mt][0] = *reinterpret_cast<const uint32_t*>(p);
            af[mt][1] = *reinterpret_cast<const uint32_t*>(p + 8 * H_STB);
            af[mt][2] = *reinterpret_cast<const uint32_t*>(p + 16);
            af[mt][3] = *reinterpret_cast<const uint32_t*>(p + 8 * H_STB + 16);
        }
        uint32_t bf[2][2];
        #pragma unroll
        for (int nt = 0; nt < 2; ++nt) {
            const char* q = sm + OFF_H + (n0s + nt * 8 + lr) * H_STB + kk * 32 + lc * 4;
            bf[nt][0] = *reinterpret_cast<const uint32_t*>(q);
            bf[nt][1] = *reinterpret_cast<const uint32_t*>(q + 16);
        }
        #pragma unroll
        for (int mt = 0; mt < 2; ++mt)
            #pragma unroll
            for (int nt = 0; nt < 2; ++nt)
                hmma(accS[mt][nt], af[mt], bf[nt]);
    }
    // store S fp32 (Ss overlays Xs[0..17408); all warps are past their last Xs read)
    #pragma unroll
    for (int mt = 0; mt < 2; ++mt) {
        #pragma unroll
        for (int nt = 0; nt < 2; ++nt) {
            int row = m0 + mt * 16 + lr;
            int col = n0s + nt * 8 + 2 * lc;
            Ss[row * S_STF + col]           = accS[mt][nt][0];
            Ss[row * S_STF + col + 1]       = accS[mt][nt][1];
            Ss[(row + 8) * S_STF + col]     = accS[mt][nt][2];
            Ss[(row + 8) * S_STF + col + 1] = accS[mt][nt][3];
        }
    }
    __syncthreads();

    // ================= softmax (fp32), write P as fp16 =====================
    // P overlays Xs[17408..26624) — disjoint from Ss, X region dead.
    {
        const int srow = tid >> 2;      // 64 rows, 4 threads/row (16 cols each)
        const int sq   = tid & 3;
        const float4* rp = reinterpret_cast<const float4*>(Ss + srow * S_STF + sq * 16);
        float v[16];
        #pragma unroll
        for (int j = 0; j < 4; ++j) {
            float4 t = rp[j];
            v[4*j] = t.x; v[4*j+1] = t.y; v[4*j+2] = t.z; v[4*j+3] = t.w;
        }
        float m = v[0];
        #pragma unroll
        for (int i = 1; i < 16; ++i) m = fmaxf(m, v[i]);
        m = fmaxf(m, __shfl_xor_sync(0xffffffffu, m, 1));
        m = fmaxf(m, __shfl_xor_sync(0xffffffffu, m, 2));
        float s = 0.f;
        #pragma unroll
        for (int i = 0; i < 16; ++i) { v[i] = __expf(v[i] - m); s += v[i]; }
        s += __shfl_xor_sync(0xffffffffu, s, 1);
        s += __shfl_xor_sync(0xffffffffu, s, 2);
        const float inv = 1.0f / s;
        uint32_t pw[8];
        #pragma unroll
        for (int j = 0; j < 8; ++j) {
            __half2 h = __floats2half2_rn(v[2*j] * inv, v[2*j+1] * inv);
            pw[j] = h2bits(h);
        }
        char* dst = sm + OFF_P + srow * P_STB + sq * 32;
        *reinterpret_cast<uint4*>(dst)      = make_uint4(pw[0], pw[1], pw[2], pw[3]);
        *reinterpret_cast<uint4*>(dst + 16) = make_uint4(pw[4], pw[5], pw[6], pw[7]);
    }
    __syncthreads();

    // ================= ctx = P(64x64) @ h(64x128), 4 k16 steps =============
    #pragma unroll
    for (int mt = 0; mt < 2; ++mt)
        #pragma unroll
        for (int nt = 0; nt < 4; ++nt)
            #pragma unroll
            for (int i = 0; i < 4; ++i) acc[mt][nt][i] = 0.f;

    #pragma unroll
    for (int kk = 0; kk < 4; ++kk) {
        uint32_t af[2][4];
        #pragma unroll
        for (int mt = 0; mt < 2; ++mt) {
            const char* p = sm + OFF_P + (m0 + mt * 16 + lr) * P_STB + kk * 32 + lc * 4;
            af[mt][0] = *reinterpret_cast<const uint32_t*>(p);
            af[mt][1] = *reinterpret_cast<const uint32_t*>(p + 8 * P_STB);
            af[mt][2] = *reinterpret_cast<const uint32_t*>(p + 16);
            af[mt][3] = *reinterpret_cast<const uint32_t*>(p + 8 * P_STB + 16);
        }
        uint32_t bf[4][2];
        #pragma unroll
        for (int nt = 0; nt < 4; ++nt) {
            const char* q = sm + OFF_T + (n0 + nt * 8 + lr) * T_STB + kk * 32 + lc * 4;
            bf[nt][0] = *reinterpret_cast<const uint32_t*>(q);
            bf[nt][1] = *reinterpret_cast<const uint32_t*>(q + 16);
        }
        #pragma unroll
        for (int mt = 0; mt < 2; ++mt)
            #pragma unroll
            for (int nt = 0; nt < 4; ++nt)
                hmma(acc[mt][nt], af[mt], bf[nt]);
    }

    // store ctx (fp32) to gmem
    #pragma unroll
    for (int mt = 0; mt < 2; ++mt) {
        #pragma unroll
        for (int nt = 0; nt < 4; ++nt) {
            size_t row = (size_t)g * SEGSZ + m0 + mt * 16 + lr;
            int col = n0 + nt * 8 + 2 * lc;
            *reinterpret_cast<float2*>(out + row * D_OUT + col) =
                make_float2(acc[mt][nt][0], acc[mt][nt][1]);
            *reinterpret_cast<float2*>(out + (row + 8) * D_OUT + col) =
                make_float2(acc[mt][nt][2], acc[mt][nt][3]);
        }
    }
}

extern "C" void kernel_launch(void* const* d_in, const int* in_sizes, int n_in,
                              void* d_out, int out_size) {
    (void)in_sizes; (void)n_in; (void)out_size;
    const float* X = (const float*)d_in[0];
    const float* W = (const float*)d_in[1];
    const float* b = (const float*)d_in[2];
    float* out = (float*)d_out;

    prep_w_kernel<<<32, 256>>>(W);   // 8192 uint2 fragments (64 KB)

    cudaFuncSetAttribute(attn_hidden_kernel,
                         cudaFuncAttributeMaxDynamicSharedMemorySize, SMEM_BYTES);
    attn_hidden_kernel<<<N_SEQ, 256, SMEM_BYTES>>>(X, b, out);
}

// round 16
// speedup vs baseline: 1.1139x; 1.1139x over previous
#include <cuda_runtime.h>
#include <cuda_fp16.h>
#include <cstdint>

#define D_IN 256
#define D_OUT 128
#define SEGSZ 64
#define N_SEQ 2048

namespace {
// Row strides in BYTES. All ≡ 16 (mod 128) so each 8-row ldmatrix tile hits
// banks 4r..4r+3 -> conflict-free.
constexpr int X_STB = 528;    // X: 256 halves + pad
constexpr int H_STB = 272;    // h row-major: 128 halves + pad
constexpr int P_STB = 144;    // P row-major: 64 halves + pad
constexpr int S_STF = 68;     // S fp32 stride in floats

// X region (33792 B) is dead after the GEMM mainloop; Ss and P overlay
// disjoint sub-ranges of it (17408 + 9216 = 26624 <= 33792).
constexpr int OFF_X  = 0;                   // 64*528  = 33792 B
constexpr int OFF_S  = 0;                   // 64*68*4 = 17408 B (overlay)
constexpr int OFF_P  = 17408;               // 64*144  =  9216 B (overlay)
constexpr int OFF_H  = 33792;               // 64*272  = 17408 B
constexpr int OFF_BS = OFF_H + 17408;       // 51200: 512 B
constexpr int SMEM_BYTES = OFF_BS + 512;    // 51712 B; x3 CTAs = 155136 B
} // namespace

// W in fp16 MMA B-fragment layout:
// g_wfrag16[(kk*16 + ng)*32 + lane] = uint2{
//   half2( W[kk*16+2lc  ][ng*8+lr], W[kk*16+2lc+1][ng*8+lr] ),
//   half2( W[kk*16+2lc+8][ng*8+lr], W[kk*16+2lc+9][ng*8+lr] ) }
__device__ uint2 g_wfrag16[16 * 16 * 32];   // 64 KB

__device__ __forceinline__ uint32_t h2bits(__half2 h) {
    return *reinterpret_cast<uint32_t*>(&h);
}

__device__ __forceinline__ void hmma(float* d, const uint32_t* a, const uint32_t* b) {
    asm volatile(
        "mma.sync.aligned.m16n8k16.row.col.f32.f16.f16.f32 "
        "{%0,%1,%2,%3}, {%4,%5,%6,%7}, {%8,%9}, {%0,%1,%2,%3};\n"
        : "+f"(d[0]), "+f"(d[1]), "+f"(d[2]), "+f"(d[3])
        : "r"(a[0]), "r"(a[1]), "r"(a[2]), "r"(a[3]), "r"(b[0]), "r"(b[1]));
}

__device__ __forceinline__ void ldsm4(uint32_t* r, uint32_t a) {
    asm volatile("ldmatrix.sync.aligned.m8n8.x4.shared.b16 {%0,%1,%2,%3}, [%4];"
        : "=r"(r[0]), "=r"(r[1]), "=r"(r[2]), "=r"(r[3]) : "r"(a));
}
__device__ __forceinline__ void ldsm2(uint32_t* r, uint32_t a) {
    asm volatile("ldmatrix.sync.aligned.m8n8.x2.shared.b16 {%0,%1}, [%2];"
        : "=r"(r[0]), "=r"(r[1]) : "r"(a));
}
__device__ __forceinline__ void ldsm2t(uint32_t* r, uint32_t a) {
    asm volatile("ldmatrix.sync.aligned.m8n8.x2.trans.shared.b16 {%0,%1}, [%2];"
        : "=r"(r[0]), "=r"(r[1]) : "r"(a));
}

__global__ __launch_bounds__(256)
void prep_w_kernel(const float* __restrict__ Wg) {
    int i = blockIdx.x * 256 + threadIdx.x;   // 0..8191
    int kk = i >> 9;          // 0..15
    int ng = (i >> 5) & 15;
    int ln = i & 31;
    int lr = ln >> 2, lc = ln & 3;
    int col = ng * 8 + lr;
    int k = kk * 16;
    __half2 b0 = __floats2half2_rn(Wg[(k + 2*lc    ) * D_OUT + col],
                                   Wg[(k + 2*lc + 1) * D_OUT + col]);
    __half2 b1 = __floats2half2_rn(Wg[(k + 2*lc + 8) * D_OUT + col],
                                   Wg[(k + 2*lc + 9) * D_OUT + col]);
    uint2 v;
    v.x = *reinterpret_cast<uint32_t*>(&b0);
    v.y = *reinterpret_cast<uint32_t*>(&b1);
    g_wfrag16[i] = v;
}

__global__ __launch_bounds__(256, 3)
void attn_hidden_kernel(const float* __restrict__ Xall,
                        const float* __restrict__ bg,
                        float* __restrict__ out)
{
    extern __shared__ char sm[];
    const uint32_t smb = (uint32_t)__cvta_generic_to_shared(sm);
    float* Ss = reinterpret_cast<float*>(sm + OFF_S);
    float* bs = reinterpret_cast<float*>(sm + OFF_BS);

    const int tid  = threadIdx.x;
    const int warp = tid >> 5;
    const int lane = tid & 31;
    const int lr   = lane >> 2;
    const int lc   = lane & 3;

    // 2x4 warp grid: GEMM/ctx warp tile = 32 rows x 32 cols; S: 32 x 16
    const int m0  = (warp & 1) * 32;
    const int nq  = warp >> 1;       // 0..3
    const int n0  = nq * 32;
    const int n0s = nq * 16;

    const int g = blockIdx.x;
    const float* Xg = Xall + (size_t)g * SEGSZ * D_IN;

    if (tid < D_OUT) bs[tid] = bg[tid];

    // ldmatrix per-lane base addresses
    // x4 (A-frags): lanes 0-15 -> rows +0..15 @ k+0; lanes 16-31 -> rows 0..15 @ k+16B
    const int l15 = lane & 15;
    const int khi = (lane >> 4) << 4;              // 0 or 16 bytes
    const uint32_t aX_base = smb + OFF_X + (m0 + l15) * X_STB + khi;
    const uint32_t aH_base = smb + OFF_H + (m0 + l15) * H_STB + khi;
    const uint32_t aP_base = smb + OFF_P + (m0 + l15) * P_STB + khi;
    // x2 (S B-frags): lanes 0-7 -> n-rows @ k+0; lanes 8-15 -> n-rows @ k+16B
    const uint32_t bS_base = smb + OFF_H + (n0s + (lane & 7)) * H_STB + (((lane >> 3) & 1) << 4);
    // x2.trans (ctx B-frags): lanes 0-15 -> h k-rows 0..15, col n0
    const uint32_t bT_base = smb + OFF_H + l15 * H_STB + n0 * 2;

    // ---- stage ALL of X (64x256) fp32 -> fp16 smem, once ----
    #pragma unroll 4
    for (int t = 0; t < 16; ++t) {
        int j = tid + t * 256;        // 0..4095 float4s (64 rows x 64 float4)
        int row = j >> 6, q = j & 63;
        float4 x4 = *reinterpret_cast<const float4*>(Xg + row * D_IN + q * 4);
        __half2 h0 = __floats2half2_rn(x4.x, x4.y);
        __half2 h1 = __floats2half2_rn(x4.z, x4.w);
        uint2 v; v.x = h2bits(h0); v.y = h2bits(h1);
        *reinterpret_cast<uint2*>(sm + OFF_X + row * X_STB + q * 8) = v;
    }

    // W B-fragment register ring: 2 slots, prefetch distance 2.
    uint32_t bfr[2][4][2];
    #pragma unroll
    for (int s = 0; s < 2; ++s) {
        #pragma unroll
        for (int nt = 0; nt < 4; ++nt) {
            uint2 w = __ldg(&g_wfrag16[(s * 16 + nq * 4 + nt) * 32 + lane]);
            bfr[s][nt][0] = w.x; bfr[s][nt][1] = w.y;
        }
    }

    __syncthreads();   // Xs + bs ready

    // ================= GEMM: h = X(64x256) @ W(256x128), 16 k16 steps ======
    float acc[2][4][4];
    #pragma unroll
    for (int mt = 0; mt < 2; ++mt)
        #pragma unroll
        for (int nt = 0; nt < 4; ++nt)
            #pragma unroll
            for (int i = 0; i < 4; ++i) acc[mt][nt][i] = 0.f;

    #pragma unroll
    for (int kk = 0; kk < 16; ++kk) {
        const int cur = kk & 1;
        uint32_t af[2][4];
        #pragma unroll
        for (int mt = 0; mt < 2; ++mt)
            ldsm4(af[mt], aX_base + mt * 16 * X_STB + kk * 32);
        #pragma unroll
        for (int mt = 0; mt < 2; ++mt)
            #pragma unroll
            for (int nt = 0; nt < 4; ++nt)
                hmma(acc[mt][nt], af[mt], bfr[cur][nt]);
        // prefetch W frags for kk+2 into the slot just consumed
        const int nk = (kk + 2 < 16) ? kk + 2 : 15;
        #pragma unroll
        for (int nt = 0; nt < 4; ++nt) {
            uint2 w = __ldg(&g_wfrag16[(nk * 16 + nq * 4 + nt) * 32 + lane]);
            bfr[cur][nt][0] = w.x; bfr[cur][nt][1] = w.y;
        }
    }

    // epilogue: h (+bias) -> fp16, row-major only (transpose handled by ldsm2t)
    #pragma unroll
    for (int mt = 0; mt < 2; ++mt) {
        #pragma unroll
        for (int nt = 0; nt < 4; ++nt) {
            int row = m0 + mt * 16 + lr;
            int col = n0 + nt * 8 + 2 * lc;
            float d0 = acc[mt][nt][0] + bs[col];
            float d1 = acc[mt][nt][1] + bs[col + 1];
            float d2 = acc[mt][nt][2] + bs[col];
            float d3 = acc[mt][nt][3] + bs[col + 1];
            __half2 p01 = __floats2half2_rn(d0, d1);
            __half2 p23 = __floats2half2_rn(d2, d3);
            *reinterpret_cast<uint32_t*>(sm + OFF_H + row * H_STB + col * 2)       = h2bits(p01);
            *reinterpret_cast<uint32_t*>(sm + OFF_H + (row + 8) * H_STB + col * 2) = h2bits(p23);
        }
    }
    __syncthreads();

    // ================= S = h @ h^T  (64x64, K=128 -> 8 k16 steps) ==========
    float accS[2][2][4];
    #pragma unroll
    for (int mt = 0; mt < 2; ++mt)
        #pragma unroll
        for (int nt = 0; nt < 2; ++nt)
            #pragma unroll
            for (int i = 0; i < 4; ++i) accS[mt][nt][i] = 0.f;

    #pragma unroll
    for (int kk = 0; kk < 8; ++kk) {
        uint32_t af[2][4];
        #pragma unroll
        for (int mt = 0; mt < 2; ++mt)
            ldsm4(af[mt], aH_base + mt * 16 * H_STB + kk * 32);
        uint32_t bf[2][2];
        #pragma unroll
        for (int nt = 0; nt < 2; ++nt)
            ldsm2(bf[nt], bS_base + nt * 8 * H_STB + kk * 32);
        #pragma unroll
        for (int mt = 0; mt < 2; ++mt)
            #pragma unroll
            for (int nt = 0; nt < 2; ++nt)
                hmma(accS[mt][nt], af[mt], bf[nt]);
    }
    // store S fp32 (Ss overlays Xs[0..17408); all warps are past their last Xs read)
    #pragma unroll
    for (int mt = 0; mt < 2; ++mt) {
        #pragma unroll
        for (int nt = 0; nt < 2; ++nt) {
            int row = m0 + mt * 16 + lr;
            int col = n0s + nt * 8 + 2 * lc;
            Ss[row * S_STF + col]           = accS[mt][nt][0];
            Ss[row * S_STF + col + 1]       = accS[mt][nt][1];
            Ss[(row + 8) * S_STF + col]     = accS[mt][nt][2];
            Ss[(row + 8) * S_STF + col + 1] = accS[mt][nt][3];
        }
    }
    __syncthreads();

    // ================= softmax (fp32), write P as fp16 =====================
    // P overlays Xs[17408..26624) — disjoint from Ss, X region dead.
    {
        const int srow = tid >> 2;      // 64 rows, 4 threads/row (16 cols each)
        const int sq   = tid & 3;
        const float4* rp = reinterpret_cast<const float4*>(Ss + srow * S_STF + sq * 16);
        float v[16];
        #pragma unroll
        for (int j = 0; j < 4; ++j) {
            float4 t = rp[j];
            v[4*j] = t.x; v[4*j+1] = t.y; v[4*j+2] = t.z; v[4*j+3] = t.w;
        }
        float m = v[0];
        #pragma unroll
        for (int i = 1; i < 16; ++i) m = fmaxf(m, v[i]);
        m = fmaxf(m, __shfl_xor_sync(0xffffffffu, m, 1));
        m = fmaxf(m, __shfl_xor_sync(0xffffffffu, m, 2));
        float s = 0.f;
        #pragma unroll
        for (int i = 0; i < 16; ++i) { v[i] = __expf(v[i] - m); s += v[i]; }
        s += __shfl_xor_sync(0xffffffffu, s, 1);
        s += __shfl_xor_sync(0xffffffffu, s, 2);
        const float inv = 1.0f / s;
        uint32_t pw[8];
        #pragma unroll
        for (int j = 0; j < 8; ++j) {
            __half2 h = __floats2half2_rn(v[2*j] * inv, v[2*j+1] * inv);
            pw[j] = h2bits(h);
        }
        char* dst = sm + OFF_P + srow * P_STB + sq * 32;
        *reinterpret_cast<uint4*>(dst)      = make_uint4(pw[0], pw[1], pw[2], pw[3]);
        *reinterpret_cast<uint4*>(dst + 16) = make_uint4(pw[4], pw[5], pw[6], pw[7]);
    }
    __syncthreads();

    // ================= ctx = P(64x64) @ h(64x128), 4 k16 steps =============
    #pragma unroll
    for (int mt = 0; mt < 2; ++mt)
        #pragma unroll
        for (int nt = 0; nt < 4; ++nt)
            #pragma unroll
            for (int i = 0; i < 4; ++i) acc[mt][nt][i] = 0.f;

    #pragma unroll
    for (int kk = 0; kk < 4; ++kk) {
        uint32_t af[2][4];
        #pragma unroll
        for (int mt = 0; mt < 2; ++mt)
            ldsm4(af[mt], aP_base + mt * 16 * P_STB + kk * 32);
        uint32_t bf[4][2];
        #pragma unroll
        for (int nt = 0; nt < 4; ++nt)
            ldsm2t(bf[nt], bT_base + kk * 16 * H_STB + nt * 16);
        #pragma unroll
        for (int mt = 0; mt < 2; ++mt)
            #pragma unroll
            for (int nt = 0; nt < 4; ++nt)
                hmma(acc[mt][nt], af[mt], bf[nt]);
    }

    // store ctx (fp32) to gmem
    #pragma unroll
    for (int mt = 0; mt < 2; ++mt) {
        #pragma unroll
        for (int nt = 0; nt < 4; ++nt) {
            size_t row = (size_t)g * SEGSZ + m0 + mt * 16 + lr;
            int col = n0 + nt * 8 + 2 * lc;
            *reinterpret_cast<float2*>(out + row * D_OUT + col) =
                make_float2(acc[mt][nt][0], acc[mt][nt][1]);
            *reinterpret_cast<float2*>(out + (row + 8) * D_OUT + col) =
                make_float2(acc[mt][nt][2], acc[mt][nt][3]);
        }
    }
}

extern "C" void kernel_launch(void* const* d_in, const int* in_sizes, int n_in,
                              void* d_out, int out_size) {
    (void)in_sizes; (void)n_in; (void)out_size;
    const float* X = (const float*)d_in[0];
    const float* W = (const float*)d_in[1];
    const float* b = (const float*)d_in[2];
    float* out = (float*)d_out;

    prep_w_kernel<<<32, 256>>>(W);   // 8192 uint2 fragments (64 KB)

    cudaFuncSetAttribute(attn_hidden_kernel,
                         cudaFuncAttributeMaxDynamicSharedMemorySize, SMEM_BYTES);
    attn_hidden_kernel<<<N_SEQ, 256, SMEM_BYTES>>>(X, b, out);
}